// round 14
// baseline (speedup 1.0000x reference)
#include <cuda_runtime.h>
#include <cuda_bf16.h>
#include <cuda_fp16.h>
#include <cstdint>
#include <math.h>

// Problem constants
#define BATCH  128
#define HEADS  4
#define SEQLEN 256
#define EMB    64
#define DQK    64
#define LHEAD  64
#define KDIM   4096   // LHEAD * EMB
#define ODIM   4096   // LHEAD * DQK
#define NTOT   (BATCH * HEADS * KDIM)

// ---------------- scratch (device globals; no allocation allowed) ----------------
__device__ __align__(16) __nv_bfloat16 g_Ahi[NTOT];   // bf16 limbs (Q,K path)
__device__ __align__(16) __nv_bfloat16 g_Alo[NTOT];
__device__ __align__(16) __half        g_Fhi[NTOT];   // fp16 limbs (V path)
__device__ __align__(16) __half        g_Flo[NTOT];
__device__ __align__(16) float g_QKV[12 * BATCH * ODIM];   // [t*4+h][b][o]

// ---------------- kernel 1: split fp32 activations into bf16 + fp16 hi/lo ----------------
__global__ void split_limbs_kernel(const float* __restrict__ x) {
    int i = blockIdx.x * blockDim.x + threadIdx.x;
    float4 v = reinterpret_cast<const float4*>(x)[i];
    __nv_bfloat16 h0 = __float2bfloat16(v.x), h1 = __float2bfloat16(v.y);
    __nv_bfloat16 h2 = __float2bfloat16(v.z), h3 = __float2bfloat16(v.w);
    __nv_bfloat16 l0 = __float2bfloat16(v.x - __bfloat162float(h0));
    __nv_bfloat16 l1 = __float2bfloat16(v.y - __bfloat162float(h1));
    __nv_bfloat16 l2 = __float2bfloat16(v.z - __bfloat162float(h2));
    __nv_bfloat16 l3 = __float2bfloat16(v.w - __bfloat162float(h3));
    __nv_bfloat162* ph = reinterpret_cast<__nv_bfloat162*>(g_Ahi);
    __nv_bfloat162* pl = reinterpret_cast<__nv_bfloat162*>(g_Alo);
    ph[2 * i]     = __halves2bfloat162(h0, h1);
    ph[2 * i + 1] = __halves2bfloat162(h2, h3);
    pl[2 * i]     = __halves2bfloat162(l0, l1);
    pl[2 * i + 1] = __halves2bfloat162(l2, l3);
    __half f0 = __float2half_rn(v.x), f1 = __float2half_rn(v.y);
    __half f2 = __float2half_rn(v.z), f3 = __float2half_rn(v.w);
    __half e0 = __float2half_rn(v.x - __half2float(f0));
    __half e1 = __float2half_rn(v.y - __half2float(f1));
    __half e2 = __float2half_rn(v.z - __half2float(f2));
    __half e3 = __float2half_rn(v.w - __half2float(f3));
    __half2* qh = reinterpret_cast<__half2*>(g_Fhi);
    __half2* ql = reinterpret_cast<__half2*>(g_Flo);
    qh[2 * i]     = __halves2half2(f0, f1);
    qh[2 * i + 1] = __halves2half2(f2, f3);
    ql[2 * i]     = __halves2half2(e0, e1);
    ql[2 * i + 1] = __halves2half2(e2, e3);
}

// ---------------- PTX helpers ----------------
__device__ __forceinline__ void cpasync16(uint32_t saddr, const void* g) {
    asm volatile("cp.async.cg.shared.global [%0], [%1], 16;"
                 :: "r"(saddr), "l"(g) : "memory");
}
#define CP_COMMIT() asm volatile("cp.async.commit_group;" ::: "memory")
#define CP_WAIT0()  asm volatile("cp.async.wait_group 0;" ::: "memory")

#define LDM_X4(R, ADDR) \
  asm volatile("ldmatrix.sync.aligned.m8n8.x4.shared.b16 {%0,%1,%2,%3}, [%4];" \
    : "=r"((R)[0]), "=r"((R)[1]), "=r"((R)[2]), "=r"((R)[3]) : "r"(ADDR))

#define MMA_BF16(C, A, Bv) \
  asm volatile("mma.sync.aligned.m16n8k16.row.col.f32.bf16.bf16.f32 " \
    "{%0,%1,%2,%3},{%4,%5,%6,%7},{%8,%9},{%0,%1,%2,%3};" \
    : "+f"((C)[0]), "+f"((C)[1]), "+f"((C)[2]), "+f"((C)[3]) \
    : "r"((A)[0]), "r"((A)[1]), "r"((A)[2]), "r"((A)[3]), "r"((Bv)[0]), "r"((Bv)[1]))

#define MMA_F16(C, A, Bv) \
  asm volatile("mma.sync.aligned.m16n8k16.row.col.f32.f16.f16.f32 " \
    "{%0,%1,%2,%3},{%4,%5,%6,%7},{%8,%9},{%0,%1,%2,%3};" \
    : "+f"((C)[0]), "+f"((C)[1]), "+f"((C)[2]), "+f"((C)[3]) \
    : "r"((A)[0]), "r"((A)[1]), "r"((A)[2]), "r"((A)[3]), "r"((Bv)[0]), "r"((Bv)[1]))

// Geometry: CTA tile 128(batch) x 64(outcols), BK=32, 2 CTAs/SM.
// Warps 0-3 consumers (64x32 each: M-split 2, N-split 2), warps 4-7 producers.
// Stage: AH [128][40], AL [128][40], WH [64][40], WL [64][40] -> 30720 B, 2 stages.
#define BKC     32
#define NITER   (KDIM / BKC)     // 128
#define OFF_AH  0
#define OFF_AL  10240
#define OFF_WH  20480
#define OFF_WL  25600
#define STAGE   30720
#define GEMM_SMEM (2 * STAGE)    // 61440 B -> 2 CTAs/SM

// ---------------- kernel 2: merged QKV projection (QK: 3-term bf16; V: 2-term fp16) ----
// grid (64, 12): y in [0,8) -> QK (t=y>>2, h=y&3); y in [8,12) -> V (h=y-8).
__global__ void __launch_bounds__(256, 2)
qkv_gemm_all(const float* __restrict__ WQp, const float* __restrict__ bQp,
             const float* __restrict__ WKp, const float* __restrict__ bKp,
             const float* __restrict__ WVp, const float* __restrict__ bVp)
{
    extern __shared__ char smraw[];
    const uint32_t base = (uint32_t)__cvta_generic_to_shared(smraw);

    const int tid  = threadIdx.x;
    const int lane = tid & 31;
    const int wid  = tid >> 5;
    const int y    = blockIdx.y;
    const bool isV = (y >= 8);
    const int warpM = (wid >> 1) * 64;     // 0 or 64
    const int warpN = (wid & 1) * 32;      // 0 or 32
    const int p = tid - 128;

    if (!isV) {
        const int t = y >> 2;
        const int h = y & 3;
        const float* Wp = (t == 0) ? WQp : WKp;
        const float* bp = ((t == 0) ? bQp : bKp) + h * ODIM + blockIdx.x * 64;
        const float* Wg = Wp + ((size_t)h * ODIM + (size_t)blockIdx.x * 64) * (size_t)KDIM;
        const __nv_bfloat16* Ahg = g_Ahi + h * KDIM;
        const __nv_bfloat16* Alg = g_Alo + h * KDIM;

        float acc[4][4][4];
#pragma unroll
        for (int a = 0; a < 4; a++)
#pragma unroll
            for (int b = 0; b < 4; b++)
#pragma unroll
                for (int c = 0; c < 4; c++) acc[a][b][c] = 0.f;

        float4 wreg[4];

#define QK_LDG(KT) do { \
    int k0 = (KT) * BKC; \
    _Pragma("unroll") \
    for (int j = 0; j < 4; j++) { \
        int f = p + 128 * j; int r = f >> 3; int c = f & 7; \
        wreg[j] = *reinterpret_cast<const float4*>(Wg + (size_t)r * KDIM + k0 + c * 4); \
    } \
} while (0)

#define QK_STS(S) do { \
    uint32_t sb = base + (uint32_t)(S) * STAGE; \
    _Pragma("unroll") \
    for (int j = 0; j < 4; j++) { \
        int f = p + 128 * j; int r = f >> 3; int c = f & 7; \
        float4 v = wreg[j]; \
        __nv_bfloat162 h0 = __floats2bfloat162_rn(v.x, v.y); \
        __nv_bfloat162 h1 = __floats2bfloat162_rn(v.z, v.w); \
        float2 f0 = __bfloat1622float2(h0); \
        float2 f1 = __bfloat1622float2(h1); \
        __nv_bfloat162 l0 = __floats2bfloat162_rn(v.x - f0.x, v.y - f0.y); \
        __nv_bfloat162 l1 = __floats2bfloat162_rn(v.z - f1.x, v.w - f1.y); \
        uint32_t off = (uint32_t)((r * 40 + c * 4) * 2); \
        asm volatile("st.shared.v2.b32 [%0], {%1,%2};" \
            :: "r"(sb + OFF_WH + off), "r"(reinterpret_cast<uint32_t&>(h0)), \
               "r"(reinterpret_cast<uint32_t&>(h1))); \
        asm volatile("st.shared.v2.b32 [%0], {%1,%2};" \
            :: "r"(sb + OFF_WL + off), "r"(reinterpret_cast<uint32_t&>(l0)), \
               "r"(reinterpret_cast<uint32_t&>(l1))); \
    } \
} while (0)

#define QK_CPA(KT, S) do { \
    uint32_t sb = base + (uint32_t)(S) * STAGE; \
    int k0 = (KT) * BKC; \
    _Pragma("unroll") \
    for (int j = 0; j < 4; j++) { \
        int f = p + 128 * j; int r = f >> 2; int c = f & 3; \
        uint32_t off = (uint32_t)(r * 80 + c * 16); \
        cpasync16(sb + OFF_AH + off, Ahg + (size_t)r * (HEADS * KDIM) + k0 + c * 8); \
        cpasync16(sb + OFF_AL + off, Alg + (size_t)r * (HEADS * KDIM) + k0 + c * 8); \
    } \
} while (0)

#define QK_COMPUTE(S) do { \
    uint32_t sB = base + (uint32_t)(S) * STAGE; \
    _Pragma("unroll") \
    for (int ks = 0; ks < 2; ks++) { \
        uint32_t ah[4][4], al[4][4], bh[4][2], bl[4][2]; \
        int arl = lane & 15; \
        int ako = ks * 16 + ((lane >> 4) << 3); \
        _Pragma("unroll") \
        for (int mi = 0; mi < 4; mi++) { \
            uint32_t off = (uint32_t)(((warpM + mi * 16 + arl) * 40 + ako) * 2); \
            LDM_X4(ah[mi], sB + OFF_AH + off); \
            LDM_X4(al[mi], sB + OFF_AL + off); \
        } \
        int bnr = ((lane >> 4) << 3) + (lane & 7); \
        int bko = ks * 16 + (((lane >> 3) & 1) << 3); \
        _Pragma("unroll") \
        for (int jj = 0; jj < 2; jj++) { \
            uint32_t off = (uint32_t)(((warpN + jj * 16 + bnr) * 40 + bko) * 2); \
            uint32_t r4[4]; \
            LDM_X4(r4, sB + OFF_WH + off); \
            bh[2 * jj][0] = r4[0]; bh[2 * jj][1] = r4[1]; \
            bh[2 * jj + 1][0] = r4[2]; bh[2 * jj + 1][1] = r4[3]; \
            LDM_X4(r4, sB + OFF_WL + off); \
            bl[2 * jj][0] = r4[0]; bl[2 * jj][1] = r4[1]; \
            bl[2 * jj + 1][0] = r4[2]; bl[2 * jj + 1][1] = r4[3]; \
        } \
        _Pragma("unroll") \
        for (int mi = 0; mi < 4; mi++) \
        _Pragma("unroll") \
        for (int nj = 0; nj < 4; nj++) MMA_BF16(acc[mi][nj], ah[mi], bh[nj]); \
        _Pragma("unroll") \
        for (int mi = 0; mi < 4; mi++) \
        _Pragma("unroll") \
        for (int nj = 0; nj < 4; nj++) MMA_BF16(acc[mi][nj], ah[mi], bl[nj]); \
        _Pragma("unroll") \
        for (int mi = 0; mi < 4; mi++) \
        _Pragma("unroll") \
        for (int nj = 0; nj < 4; nj++) MMA_BF16(acc[mi][nj], al[mi], bh[nj]); \
    } \
} while (0)

        if (wid >= 4) {
            QK_LDG(0);
            QK_STS(0);
            QK_CPA(0, 0);
            CP_COMMIT();
            QK_LDG(1);
            CP_WAIT0();
        }
        __syncthreads();

        for (int kt = 0; kt < NITER; kt++) {
            if (wid < 4) {
                QK_COMPUTE(kt & 1);
            } else {
                if (kt + 1 < NITER) {
                    QK_STS((kt + 1) & 1);
                    QK_CPA(kt + 1, (kt + 1) & 1);
                    CP_COMMIT();
                    if (kt + 2 < NITER) QK_LDG(kt + 2);
                    CP_WAIT0();
                }
            }
            __syncthreads();
        }

        if (wid < 4) {
            float* outB = g_QKV + (size_t)y * 128 * ODIM + blockIdx.x * 64;
            const int g = lane >> 2;
            const int q = lane & 3;
#pragma unroll
            for (int nj = 0; nj < 4; nj++) {
                int col = warpN + nj * 8 + 2 * q;
                float b0 = bp[col];
                float b1 = bp[col + 1];
#pragma unroll
                for (int mi = 0; mi < 4; mi++) {
                    int r0 = warpM + mi * 16 + g;
                    float2 v0; v0.x = acc[mi][nj][0] + b0; v0.y = acc[mi][nj][1] + b1;
                    float2 v1; v1.x = acc[mi][nj][2] + b0; v1.y = acc[mi][nj][3] + b1;
                    *reinterpret_cast<float2*>(outB + (size_t)r0 * ODIM + col) = v0;
                    *reinterpret_cast<float2*>(outB + (size_t)(r0 + 8) * ODIM + col) = v1;
                }
            }
        }
    } else {
        // ---------------- V path: 2-term fp16 ----------------
        const int h = y - 8;
        const float* bp = bVp + h * ODIM + blockIdx.x * 64;
        const float* Wg = WVp + ((size_t)h * ODIM + (size_t)blockIdx.x * 64) * (size_t)KDIM;
        const __half* Ahg = g_Fhi + h * KDIM;
        const __half* Alg = g_Flo + h * KDIM;

        float acc[4][4][4];
#pragma unroll
        for (int a = 0; a < 4; a++)
#pragma unroll
            for (int b = 0; b < 4; b++)
#pragma unroll
                for (int c = 0; c < 4; c++) acc[a][b][c] = 0.f;

        float4 wreg[4];

#define V_LDG(KT) do { \
    int k0 = (KT) * BKC; \
    _Pragma("unroll") \
    for (int j = 0; j < 4; j++) { \
        int f = p + 128 * j; int r = f >> 3; int c = f & 7; \
        wreg[j] = *reinterpret_cast<const float4*>(Wg + (size_t)r * KDIM + k0 + c * 4); \
    } \
} while (0)

#define V_STS(S) do { \
    uint32_t sb = base + (uint32_t)(S) * STAGE; \
    _Pragma("unroll") \
    for (int j = 0; j < 4; j++) { \
        int f = p + 128 * j; int r = f >> 3; int c = f & 7; \
        float4 v = wreg[j]; \
        __half2 h0 = __floats2half2_rn(v.x, v.y); \
        __half2 h1 = __floats2half2_rn(v.z, v.w); \
        uint32_t off = (uint32_t)((r * 40 + c * 4) * 2); \
        asm volatile("st.shared.v2.b32 [%0], {%1,%2};" \
            :: "r"(sb + OFF_WH + off), "r"(reinterpret_cast<uint32_t&>(h0)), \
               "r"(reinterpret_cast<uint32_t&>(h1))); \
    } \
} while (0)

#define V_CPA(KT, S) do { \
    uint32_t sb = base + (uint32_t)(S) * STAGE; \
    int k0 = (KT) * BKC; \
    _Pragma("unroll") \
    for (int j = 0; j < 4; j++) { \
        int f = p + 128 * j; int r = f >> 2; int c = f & 3; \
        uint32_t off = (uint32_t)(r * 80 + c * 16); \
        cpasync16(sb + OFF_AH + off, Ahg + (size_t)r * (HEADS * KDIM) + k0 + c * 8); \
        cpasync16(sb + OFF_AL + off, Alg + (size_t)r * (HEADS * KDIM) + k0 + c * 8); \
    } \
} while (0)

#define V_COMPUTE(S) do { \
    uint32_t sB = base + (uint32_t)(S) * STAGE; \
    _Pragma("unroll") \
    for (int ks = 0; ks < 2; ks++) { \
        uint32_t ah[4][4], al[4][4], bh[4][2]; \
        int arl = lane & 15; \
        int ako = ks * 16 + ((lane >> 4) << 3); \
        _Pragma("unroll") \
        for (int mi = 0; mi < 4; mi++) { \
            uint32_t off = (uint32_t)(((warpM + mi * 16 + arl) * 40 + ako) * 2); \
            LDM_X4(ah[mi], sB + OFF_AH + off); \
            LDM_X4(al[mi], sB + OFF_AL + off); \
        } \
        int bnr = ((lane >> 4) << 3) + (lane & 7); \
        int bko = ks * 16 + (((lane >> 3) & 1) << 3); \
        _Pragma("unroll") \
        for (int jj = 0; jj < 2; jj++) { \
            uint32_t off = (uint32_t)(((warpN + jj * 16 + bnr) * 40 + bko) * 2); \
            uint32_t r4[4]; \
            LDM_X4(r4, sB + OFF_WH + off); \
            bh[2 * jj][0] = r4[0]; bh[2 * jj][1] = r4[1]; \
            bh[2 * jj + 1][0] = r4[2]; bh[2 * jj + 1][1] = r4[3]; \
        } \
        _Pragma("unroll") \
        for (int mi = 0; mi < 4; mi++) \
        _Pragma("unroll") \
        for (int nj = 0; nj < 4; nj++) MMA_F16(acc[mi][nj], ah[mi], bh[nj]); \
        _Pragma("unroll") \
        for (int mi = 0; mi < 4; mi++) \
        _Pragma("unroll") \
        for (int nj = 0; nj < 4; nj++) MMA_F16(acc[mi][nj], al[mi], bh[nj]); \
    } \
} while (0)

        if (wid >= 4) {
            V_LDG(0);
            V_STS(0);
            V_CPA(0, 0);
            CP_COMMIT();
            V_LDG(1);
            CP_WAIT0();
        }
        __syncthreads();

        for (int kt = 0; kt < NITER; kt++) {
            if (wid < 4) {
                V_COMPUTE(kt & 1);
            } else {
                if (kt + 1 < NITER) {
                    V_STS((kt + 1) & 1);
                    V_CPA(kt + 1, (kt + 1) & 1);
                    CP_COMMIT();
                    if (kt + 2 < NITER) V_LDG(kt + 2);
                    CP_WAIT0();
                }
            }
            __syncthreads();
        }

        if (wid < 4) {
            float* outB = g_QKV + (size_t)(8 + h) * 128 * ODIM + blockIdx.x * 64;
            const int g = lane >> 2;
            const int q = lane & 3;
#pragma unroll
            for (int nj = 0; nj < 4; nj++) {
                int col = warpN + nj * 8 + 2 * q;
                float b0 = bp[col];
                float b1 = bp[col + 1];
#pragma unroll
                for (int mi = 0; mi < 4; mi++) {
                    int r0 = warpM + mi * 16 + g;
                    float2 v0; v0.x = acc[mi][nj][0] + b0; v0.y = acc[mi][nj][1] + b1;
                    float2 v1; v1.x = acc[mi][nj][2] + b0; v1.y = acc[mi][nj][3] + b1;
                    *reinterpret_cast<float2*>(outB + (size_t)r0 * ODIM + col) = v0;
                    *reinterpret_cast<float2*>(outB + (size_t)(r0 + 8) * ODIM + col) = v1;
                }
            }
        }
    }
}

// ---------------- kernel 3: local attention, conflict-free layouts ----------------
#define SPAD 72
#define ATTN_SMEM ((2 * 64 * SPAD + 2 * 64 * 64 + 512) * 4)

__global__ void __launch_bounds__(256)
attn_kernel(float* __restrict__ out)
{
    extern __shared__ float smf[];
    float* Qs  = smf;                         // [64][SPAD]
    float* Ss  = smf + 64 * SPAD;             // [64][SPAD]
    float* Kt  = smf + 2 * 64 * SPAD;         // [64][64]  Kt[d][k]
    float* Vs  = Kt + 64 * 64;                // [64][64]
    float* red = Vs + 64 * 64;                // [512]

    const int b = blockIdx.x >> 2;
    const int h = blockIdx.x & 3;
    const int tid = threadIdx.x;
    const float* Qg = g_QKV + ((size_t)(0 * 4 + h) * BATCH + b) * ODIM;
    const float* Kg = g_QKV + ((size_t)(1 * 4 + h) * BATCH + b) * ODIM;
    const float* Vg = g_QKV + ((size_t)(2 * 4 + h) * BATCH + b) * ODIM;

#pragma unroll
    for (int j = 0; j < 4; j++) {
        int f = tid + 256 * j;
        int r = f >> 4;
        int c = (f & 15) * 4;
        float4 qv = *reinterpret_cast<const float4*>(Qg + r * 64 + c);
        float4 vv = *reinterpret_cast<const float4*>(Vg + r * 64 + c);
        *reinterpret_cast<float4*>(Qs + r * SPAD + c) = qv;
        *reinterpret_cast<float4*>(Vs + r * 64 + c) = vv;
        int kr = f & 63;
        int c4 = (f >> 6) * 4;
        float4 kv = *reinterpret_cast<const float4*>(Kg + kr * 64 + c4);
        Kt[(c4 + 0) * 64 + kr] = kv.x;
        Kt[(c4 + 1) * 64 + kr] = kv.y;
        Kt[(c4 + 2) * 64 + kr] = kv.z;
        Kt[(c4 + 3) * 64 + kr] = kv.w;
    }
    __syncthreads();

    const int tx = tid & 15, ty = tid >> 4;
    const int q0 = ty * 4, k0 = tx * 4;

    float s[4][4];
#pragma unroll
    for (int i = 0; i < 4; i++)
#pragma unroll
        for (int j = 0; j < 4; j++) s[i][j] = 0.f;

    for (int d = 0; d < 64; d += 4) {
        float4 q4[4];
#pragma unroll
        for (int i = 0; i < 4; i++)
            q4[i] = *reinterpret_cast<const float4*>(Qs + (q0 + i) * SPAD + d);
#pragma unroll
        for (int dd = 0; dd < 4; dd++) {
            float4 kv = *reinterpret_cast<const float4*>(Kt + (d + dd) * 64 + k0);
#pragma unroll
            for (int i = 0; i < 4; i++) {
                float qv = (&q4[i].x)[dd];
                s[i][0] = fmaf(qv, kv.x, s[i][0]);
                s[i][1] = fmaf(qv, kv.y, s[i][1]);
                s[i][2] = fmaf(qv, kv.z, s[i][2]);
                s[i][3] = fmaf(qv, kv.w, s[i][3]);
            }
        }
    }
#pragma unroll
    for (int i = 0; i < 4; i++) {
        int qq = q0 + i;
        float4 o;
        o.x = s[i][0] - ((k0 + 0 > qq) ? 1e20f : 0.f);
        o.y = s[i][1] - ((k0 + 1 > qq) ? 1e20f : 0.f);
        o.z = s[i][2] - ((k0 + 2 > qq) ? 1e20f : 0.f);
        o.w = s[i][3] - ((k0 + 3 > qq) ? 1e20f : 0.f);
        *reinterpret_cast<float4*>(Ss + qq * SPAD + k0) = o;
    }
    __syncthreads();

    {
        const int kk = tid & 63;
        const int seg = tid >> 6;
        const int qb = seg * 16;
        float m = -3.4e38f;
#pragma unroll
        for (int i = 0; i < 16; i++) m = fmaxf(m, Ss[(qb + i) * SPAD + kk]);
        red[seg * 64 + kk] = m;
        __syncthreads();
        float M = fmaxf(fmaxf(red[kk], red[64 + kk]), fmaxf(red[128 + kk], red[192 + kk]));
        float ssum = 0.f;
#pragma unroll
        for (int i = 0; i < 16; i++) {
            float e = expf(Ss[(qb + i) * SPAD + kk] - M);
            Ss[(qb + i) * SPAD + kk] = e;
            ssum += e;
        }
        red[256 + seg * 64 + kk] = ssum;
        __syncthreads();
        float inv = 1.f / (red[256 + kk] + red[320 + kk] + red[384 + kk] + red[448 + kk]);
#pragma unroll
        for (int i = 0; i < 16; i++) Ss[(qb + i) * SPAD + kk] *= inv;
    }
    __syncthreads();

    const int d0 = tx * 4;
    float z[4][4];
#pragma unroll
    for (int i = 0; i < 4; i++)
#pragma unroll
        for (int j = 0; j < 4; j++) z[i][j] = 0.f;

    for (int k = 0; k < 64; k++) {
        float4 vv = *reinterpret_cast<const float4*>(Vs + k * 64 + d0);
        float av[4];
#pragma unroll
        for (int i = 0; i < 4; i++) av[i] = Ss[(q0 + i) * SPAD + k];
#pragma unroll
        for (int i = 0; i < 4; i++) {
            z[i][0] = fmaf(av[i], vv.x, z[i][0]);
            z[i][1] = fmaf(av[i], vv.y, z[i][1]);
            z[i][2] = fmaf(av[i], vv.z, z[i][2]);
            z[i][3] = fmaf(av[i], vv.w, z[i][3]);
        }
    }

    float* og = out + ((size_t)b * SEQLEN + h * LHEAD) * DQK;
#pragma unroll
    for (int i = 0; i < 4; i++) {
        float4 o4;
        o4.x = z[i][0] * 0.125f;
        o4.y = z[i][1] * 0.125f;
        o4.z = z[i][2] * 0.125f;
        o4.w = z[i][3] * 0.125f;
        *reinterpret_cast<float4*>(og + (q0 + i) * 64 + d0) = o4;
    }
}

// ---------------- launch ----------------
extern "C" void kernel_launch(void* const* d_in, const int* in_sizes, int n_in,
                              void* d_out, int out_size) {
    const float* seq = (const float*)d_in[0];
    const float* WQ  = (const float*)d_in[1];
    const float* bQ  = (const float*)d_in[2];
    const float* WK  = (const float*)d_in[3];
    const float* bK  = (const float*)d_in[4];
    const float* WV  = (const float*)d_in[5];
    const float* bV  = (const float*)d_in[6];
    float* out = (float*)d_out;

    cudaFuncSetAttribute(qkv_gemm_all, cudaFuncAttributeMaxDynamicSharedMemorySize, GEMM_SMEM);
    cudaFuncSetAttribute(attn_kernel, cudaFuncAttributeMaxDynamicSharedMemorySize, ATTN_SMEM);

    split_limbs_kernel<<<NTOT / 4 / 256, 256>>>(seq);
    qkv_gemm_all<<<dim3(64, 12), 256, GEMM_SMEM>>>(WQ, bQ, WK, bK, WV, bV);
    attn_kernel<<<BATCH * HEADS, 256, ATTN_SMEM>>>(out);
}

// round 15
// speedup vs baseline: 1.3907x; 1.3907x over previous
#include <cuda_runtime.h>
#include <cuda_bf16.h>
#include <cuda_fp16.h>
#include <cstdint>
#include <math.h>

// Problem constants
#define BATCH  128
#define HEADS  4
#define SEQLEN 256
#define EMB    64
#define DQK    64
#define LHEAD  64
#define KDIM   4096   // LHEAD * EMB
#define ODIM   4096   // LHEAD * DQK
#define NTOT   (BATCH * HEADS * KDIM)

// ---------------- scratch (device globals; no allocation allowed) ----------------
__device__ __align__(16) __nv_bfloat16 g_Ahi[NTOT];   // bf16 limbs (Q,K path)
__device__ __align__(16) __nv_bfloat16 g_Alo[NTOT];
__device__ __align__(16) __half        g_Fhi[NTOT];   // fp16 limbs (V path)
__device__ __align__(16) __half        g_Flo[NTOT];
__device__ __align__(16) float g_QKV[12 * BATCH * ODIM];   // [t*4+h][b][o]

// ---------------- kernel 1: split fp32 activations into bf16 + fp16 hi/lo ----------------
__global__ void split_limbs_kernel(const float* __restrict__ x) {
    int i = blockIdx.x * blockDim.x + threadIdx.x;
    float4 v = reinterpret_cast<const float4*>(x)[i];
    __nv_bfloat16 h0 = __float2bfloat16(v.x), h1 = __float2bfloat16(v.y);
    __nv_bfloat16 h2 = __float2bfloat16(v.z), h3 = __float2bfloat16(v.w);
    __nv_bfloat16 l0 = __float2bfloat16(v.x - __bfloat162float(h0));
    __nv_bfloat16 l1 = __float2bfloat16(v.y - __bfloat162float(h1));
    __nv_bfloat16 l2 = __float2bfloat16(v.z - __bfloat162float(h2));
    __nv_bfloat16 l3 = __float2bfloat16(v.w - __bfloat162float(h3));
    __nv_bfloat162* ph = reinterpret_cast<__nv_bfloat162*>(g_Ahi);
    __nv_bfloat162* pl = reinterpret_cast<__nv_bfloat162*>(g_Alo);
    ph[2 * i]     = __halves2bfloat162(h0, h1);
    ph[2 * i + 1] = __halves2bfloat162(h2, h3);
    pl[2 * i]     = __halves2bfloat162(l0, l1);
    pl[2 * i + 1] = __halves2bfloat162(l2, l3);
    __half f0 = __float2half_rn(v.x), f1 = __float2half_rn(v.y);
    __half f2 = __float2half_rn(v.z), f3 = __float2half_rn(v.w);
    __half e0 = __float2half_rn(v.x - __half2float(f0));
    __half e1 = __float2half_rn(v.y - __half2float(f1));
    __half e2 = __float2half_rn(v.z - __half2float(f2));
    __half e3 = __float2half_rn(v.w - __half2float(f3));
    __half2* qh = reinterpret_cast<__half2*>(g_Fhi);
    __half2* ql = reinterpret_cast<__half2*>(g_Flo);
    qh[2 * i]     = __halves2half2(f0, f1);
    qh[2 * i + 1] = __halves2half2(f2, f3);
    ql[2 * i]     = __halves2half2(e0, e1);
    ql[2 * i + 1] = __halves2half2(e2, e3);
}

// ---------------- PTX helpers ----------------
__device__ __forceinline__ void cpasync16(uint32_t saddr, const void* g) {
    asm volatile("cp.async.cg.shared.global [%0], [%1], 16;"
                 :: "r"(saddr), "l"(g) : "memory");
}
#define CP_COMMIT() asm volatile("cp.async.commit_group;" ::: "memory")
#define CP_WAIT0()  asm volatile("cp.async.wait_group 0;" ::: "memory")

#define LDM_X4(R, ADDR) \
  asm volatile("ldmatrix.sync.aligned.m8n8.x4.shared.b16 {%0,%1,%2,%3}, [%4];" \
    : "=r"((R)[0]), "=r"((R)[1]), "=r"((R)[2]), "=r"((R)[3]) : "r"(ADDR))

#define MMA_BF16(C, A, Bv) \
  asm volatile("mma.sync.aligned.m16n8k16.row.col.f32.bf16.bf16.f32 " \
    "{%0,%1,%2,%3},{%4,%5,%6,%7},{%8,%9},{%0,%1,%2,%3};" \
    : "+f"((C)[0]), "+f"((C)[1]), "+f"((C)[2]), "+f"((C)[3]) \
    : "r"((A)[0]), "r"((A)[1]), "r"((A)[2]), "r"((A)[3]), "r"((Bv)[0]), "r"((Bv)[1]))

#define MMA_F16(C, A, Bv) \
  asm volatile("mma.sync.aligned.m16n8k16.row.col.f32.f16.f16.f32 " \
    "{%0,%1,%2,%3},{%4,%5,%6,%7},{%8,%9},{%0,%1,%2,%3};" \
    : "+f"((C)[0]), "+f"((C)[1]), "+f"((C)[2]), "+f"((C)[3]) \
    : "r"((A)[0]), "r"((A)[1]), "r"((A)[2]), "r"((A)[3]), "r"((Bv)[0]), "r"((Bv)[1]))

// Geometry: CTA tile 128(batch) x 128(outcols), BK=32, 384 threads.
// Warps 0-7: consumers, 64x32 each (warpM = (wid&1)*64, warpN = (wid>>1)*32)
//   -> 2 consumer warps per SMSP = 2 independent MMA streams.
// Warps 8-11: producers (identical work split to R13's 4 producer warps).
// Stage: AH [128][40], AL [128][40], WH [128][40], WL [128][40] -> 40960 B, 2 stages.
#define BKC     32
#define NITER   (KDIM / BKC)     // 128
#define OFF_AH  0
#define OFF_AL  10240
#define OFF_WH  20480
#define OFF_WL  30720
#define STAGE   40960
#define GEMM_SMEM (2 * STAGE)    // 81920 B

// ---------------- kernel 2: merged QKV projection (QK: 3-term bf16; V: 2-term fp16) ----
// grid (32, 12): y in [0,8) -> QK (t=y>>2, h=y&3); y in [8,12) -> V (h=y-8).
__global__ void __launch_bounds__(384, 1)
qkv_gemm_all(const float* __restrict__ WQp, const float* __restrict__ bQp,
             const float* __restrict__ WKp, const float* __restrict__ bKp,
             const float* __restrict__ WVp, const float* __restrict__ bVp)
{
    extern __shared__ char smraw[];
    const uint32_t base = (uint32_t)__cvta_generic_to_shared(smraw);

    const int tid  = threadIdx.x;
    const int lane = tid & 31;
    const int wid  = tid >> 5;
    const int y    = blockIdx.y;
    const bool isV = (y >= 8);
    const int warpM = (wid & 1) * 64;       // 0 or 64
    const int warpN = (wid >> 1) * 32;      // 0,32,64,96 (consumers wid<8)
    const int p = tid - 256;                // producer thread index (wid 8..11)

    if (!isV) {
        const int t = y >> 2;
        const int h = y & 3;
        const float* Wp = (t == 0) ? WQp : WKp;
        const float* bp = ((t == 0) ? bQp : bKp) + h * ODIM + blockIdx.x * 128;
        const float* Wg = Wp + ((size_t)h * ODIM + (size_t)blockIdx.x * 128) * (size_t)KDIM;
        const __nv_bfloat16* Ahg = g_Ahi + h * KDIM;
        const __nv_bfloat16* Alg = g_Alo + h * KDIM;

        float acc[4][4][4];
#pragma unroll
        for (int a = 0; a < 4; a++)
#pragma unroll
            for (int b = 0; b < 4; b++)
#pragma unroll
                for (int c = 0; c < 4; c++) acc[a][b][c] = 0.f;

        float4 wreg[8];

#define QK_LDG(KT) do { \
    int k0 = (KT) * BKC; \
    _Pragma("unroll") \
    for (int j = 0; j < 8; j++) { \
        int f = p + 128 * j; int r = f >> 3; int c = f & 7; \
        wreg[j] = *reinterpret_cast<const float4*>(Wg + (size_t)r * KDIM + k0 + c * 4); \
    } \
} while (0)

#define QK_STS(S) do { \
    uint32_t sb = base + (uint32_t)(S) * STAGE; \
    _Pragma("unroll") \
    for (int j = 0; j < 8; j++) { \
        int f = p + 128 * j; int r = f >> 3; int c = f & 7; \
        float4 v = wreg[j]; \
        __nv_bfloat162 h0 = __floats2bfloat162_rn(v.x, v.y); \
        __nv_bfloat162 h1 = __floats2bfloat162_rn(v.z, v.w); \
        float2 f0 = __bfloat1622float2(h0); \
        float2 f1 = __bfloat1622float2(h1); \
        __nv_bfloat162 l0 = __floats2bfloat162_rn(v.x - f0.x, v.y - f0.y); \
        __nv_bfloat162 l1 = __floats2bfloat162_rn(v.z - f1.x, v.w - f1.y); \
        uint32_t off = (uint32_t)((r * 40 + c * 4) * 2); \
        asm volatile("st.shared.v2.b32 [%0], {%1,%2};" \
            :: "r"(sb + OFF_WH + off), "r"(reinterpret_cast<uint32_t&>(h0)), \
               "r"(reinterpret_cast<uint32_t&>(h1))); \
        asm volatile("st.shared.v2.b32 [%0], {%1,%2};" \
            :: "r"(sb + OFF_WL + off), "r"(reinterpret_cast<uint32_t&>(l0)), \
               "r"(reinterpret_cast<uint32_t&>(l1))); \
    } \
} while (0)

#define QK_CPA(KT, S) do { \
    uint32_t sb = base + (uint32_t)(S) * STAGE; \
    int k0 = (KT) * BKC; \
    _Pragma("unroll") \
    for (int j = 0; j < 4; j++) { \
        int f = p + 128 * j; int r = f >> 2; int c = f & 3; \
        uint32_t off = (uint32_t)(r * 80 + c * 16); \
        cpasync16(sb + OFF_AH + off, Ahg + (size_t)r * (HEADS * KDIM) + k0 + c * 8); \
        cpasync16(sb + OFF_AL + off, Alg + (size_t)r * (HEADS * KDIM) + k0 + c * 8); \
    } \
} while (0)

#define QK_COMPUTE(S) do { \
    uint32_t sB = base + (uint32_t)(S) * STAGE; \
    _Pragma("unroll") \
    for (int ks = 0; ks < 2; ks++) { \
        uint32_t ah[4][4], al[4][4], bh[4][2], bl[4][2]; \
        int arl = lane & 15; \
        int ako = ks * 16 + ((lane >> 4) << 3); \
        _Pragma("unroll") \
        for (int mi = 0; mi < 4; mi++) { \
            uint32_t off = (uint32_t)(((warpM + mi * 16 + arl) * 40 + ako) * 2); \
            LDM_X4(ah[mi], sB + OFF_AH + off); \
            LDM_X4(al[mi], sB + OFF_AL + off); \
        } \
        int bnr = ((lane >> 4) << 3) + (lane & 7); \
        int bko = ks * 16 + (((lane >> 3) & 1) << 3); \
        _Pragma("unroll") \
        for (int jj = 0; jj < 2; jj++) { \
            uint32_t off = (uint32_t)(((warpN + jj * 16 + bnr) * 40 + bko) * 2); \
            uint32_t r4[4]; \
            LDM_X4(r4, sB + OFF_WH + off); \
            bh[2 * jj][0] = r4[0]; bh[2 * jj][1] = r4[1]; \
            bh[2 * jj + 1][0] = r4[2]; bh[2 * jj + 1][1] = r4[3]; \
            LDM_X4(r4, sB + OFF_WL + off); \
            bl[2 * jj][0] = r4[0]; bl[2 * jj][1] = r4[1]; \
            bl[2 * jj + 1][0] = r4[2]; bl[2 * jj + 1][1] = r4[3]; \
        } \
        _Pragma("unroll") \
        for (int mi = 0; mi < 4; mi++) \
        _Pragma("unroll") \
        for (int nj = 0; nj < 4; nj++) MMA_BF16(acc[mi][nj], ah[mi], bh[nj]); \
        _Pragma("unroll") \
        for (int mi = 0; mi < 4; mi++) \
        _Pragma("unroll") \
        for (int nj = 0; nj < 4; nj++) MMA_BF16(acc[mi][nj], ah[mi], bl[nj]); \
        _Pragma("unroll") \
        for (int mi = 0; mi < 4; mi++) \
        _Pragma("unroll") \
        for (int nj = 0; nj < 4; nj++) MMA_BF16(acc[mi][nj], al[mi], bh[nj]); \
    } \
} while (0)

        if (wid >= 8) {
            QK_LDG(0);
            QK_STS(0);
            QK_CPA(0, 0);
            CP_COMMIT();
            QK_LDG(1);
            CP_WAIT0();
        }
        __syncthreads();

        for (int kt = 0; kt < NITER; kt++) {
            if (wid < 8) {
                QK_COMPUTE(kt & 1);
            } else {
                if (kt + 1 < NITER) {
                    QK_STS((kt + 1) & 1);
                    QK_CPA(kt + 1, (kt + 1) & 1);
                    CP_COMMIT();
                    if (kt + 2 < NITER) QK_LDG(kt + 2);
                    CP_WAIT0();
                }
            }
            __syncthreads();
        }

        if (wid < 8) {
            float* outB = g_QKV + (size_t)y * 128 * ODIM + blockIdx.x * 128;
            const int g = lane >> 2;
            const int q = lane & 3;
#pragma unroll
            for (int nj = 0; nj < 4; nj++) {
                int col = warpN + nj * 8 + 2 * q;
                float b0 = bp[col];
                float b1 = bp[col + 1];
#pragma unroll
                for (int mi = 0; mi < 4; mi++) {
                    int r0 = warpM + mi * 16 + g;
                    float2 v0; v0.x = acc[mi][nj][0] + b0; v0.y = acc[mi][nj][1] + b1;
                    float2 v1; v1.x = acc[mi][nj][2] + b0; v1.y = acc[mi][nj][3] + b1;
                    *reinterpret_cast<float2*>(outB + (size_t)r0 * ODIM + col) = v0;
                    *reinterpret_cast<float2*>(outB + (size_t)(r0 + 8) * ODIM + col) = v1;
                }
            }
        }
    } else {
        // ---------------- V path: 2-term fp16 ----------------
        const int h = y - 8;
        const float* bp = bVp + h * ODIM + blockIdx.x * 128;
        const float* Wg = WVp + ((size_t)h * ODIM + (size_t)blockIdx.x * 128) * (size_t)KDIM;
        const __half* Ahg = g_Fhi + h * KDIM;
        const __half* Alg = g_Flo + h * KDIM;

        float acc[4][4][4];
#pragma unroll
        for (int a = 0; a < 4; a++)
#pragma unroll
            for (int b = 0; b < 4; b++)
#pragma unroll
                for (int c = 0; c < 4; c++) acc[a][b][c] = 0.f;

        float4 wreg[8];

#define V_LDG(KT) do { \
    int k0 = (KT) * BKC; \
    _Pragma("unroll") \
    for (int j = 0; j < 8; j++) { \
        int f = p + 128 * j; int r = f >> 3; int c = f & 7; \
        wreg[j] = *reinterpret_cast<const float4*>(Wg + (size_t)r * KDIM + k0 + c * 4); \
    } \
} while (0)

#define V_STS(S) do { \
    uint32_t sb = base + (uint32_t)(S) * STAGE; \
    _Pragma("unroll") \
    for (int j = 0; j < 8; j++) { \
        int f = p + 128 * j; int r = f >> 3; int c = f & 7; \
        float4 v = wreg[j]; \
        __half2 h0 = __floats2half2_rn(v.x, v.y); \
        __half2 h1 = __floats2half2_rn(v.z, v.w); \
        uint32_t off = (uint32_t)((r * 40 + c * 4) * 2); \
        asm volatile("st.shared.v2.b32 [%0], {%1,%2};" \
            :: "r"(sb + OFF_WH + off), "r"(reinterpret_cast<uint32_t&>(h0)), \
               "r"(reinterpret_cast<uint32_t&>(h1))); \
    } \
} while (0)

#define V_CPA(KT, S) do { \
    uint32_t sb = base + (uint32_t)(S) * STAGE; \
    int k0 = (KT) * BKC; \
    _Pragma("unroll") \
    for (int j = 0; j < 4; j++) { \
        int f = p + 128 * j; int r = f >> 2; int c = f & 3; \
        uint32_t off = (uint32_t)(r * 80 + c * 16); \
        cpasync16(sb + OFF_AH + off, Ahg + (size_t)r * (HEADS * KDIM) + k0 + c * 8); \
        cpasync16(sb + OFF_AL + off, Alg + (size_t)r * (HEADS * KDIM) + k0 + c * 8); \
    } \
} while (0)

#define V_COMPUTE(S) do { \
    uint32_t sB = base + (uint32_t)(S) * STAGE; \
    _Pragma("unroll") \
    for (int ks = 0; ks < 2; ks++) { \
        uint32_t ah[4][4], al[4][4], bh[4][2]; \
        int arl = lane & 15; \
        int ako = ks * 16 + ((lane >> 4) << 3); \
        _Pragma("unroll") \
        for (int mi = 0; mi < 4; mi++) { \
            uint32_t off = (uint32_t)(((warpM + mi * 16 + arl) * 40 + ako) * 2); \
            LDM_X4(ah[mi], sB + OFF_AH + off); \
            LDM_X4(al[mi], sB + OFF_AL + off); \
        } \
        int bnr = ((lane >> 4) << 3) + (lane & 7); \
        int bko = ks * 16 + (((lane >> 3) & 1) << 3); \
        _Pragma("unroll") \
        for (int jj = 0; jj < 2; jj++) { \
            uint32_t off = (uint32_t)(((warpN + jj * 16 + bnr) * 40 + bko) * 2); \
            uint32_t r4[4]; \
            LDM_X4(r4, sB + OFF_WH + off); \
            bh[2 * jj][0] = r4[0]; bh[2 * jj][1] = r4[1]; \
            bh[2 * jj + 1][0] = r4[2]; bh[2 * jj + 1][1] = r4[3]; \
        } \
        _Pragma("unroll") \
        for (int mi = 0; mi < 4; mi++) \
        _Pragma("unroll") \
        for (int nj = 0; nj < 4; nj++) MMA_F16(acc[mi][nj], ah[mi], bh[nj]); \
        _Pragma("unroll") \
        for (int mi = 0; mi < 4; mi++) \
        _Pragma("unroll") \
        for (int nj = 0; nj < 4; nj++) MMA_F16(acc[mi][nj], al[mi], bh[nj]); \
    } \
} while (0)

        if (wid >= 8) {
            V_LDG(0);
            V_STS(0);
            V_CPA(0, 0);
            CP_COMMIT();
            V_LDG(1);
            CP_WAIT0();
        }
        __syncthreads();

        for (int kt = 0; kt < NITER; kt++) {
            if (wid < 8) {
                V_COMPUTE(kt & 1);
            } else {
                if (kt + 1 < NITER) {
                    V_STS((kt + 1) & 1);
                    V_CPA(kt + 1, (kt + 1) & 1);
                    CP_COMMIT();
                    if (kt + 2 < NITER) V_LDG(kt + 2);
                    CP_WAIT0();
                }
            }
            __syncthreads();
        }

        if (wid < 8) {
            float* outB = g_QKV + (size_t)(8 + h) * 128 * ODIM + blockIdx.x * 128;
            const int g = lane >> 2;
            const int q = lane & 3;
#pragma unroll
            for (int nj = 0; nj < 4; nj++) {
                int col = warpN + nj * 8 + 2 * q;
                float b0 = bp[col];
                float b1 = bp[col + 1];
#pragma unroll
                for (int mi = 0; mi < 4; mi++) {
                    int r0 = warpM + mi * 16 + g;
                    float2 v0; v0.x = acc[mi][nj][0] + b0; v0.y = acc[mi][nj][1] + b1;
                    float2 v1; v1.x = acc[mi][nj][2] + b0; v1.y = acc[mi][nj][3] + b1;
                    *reinterpret_cast<float2*>(outB + (size_t)r0 * ODIM + col) = v0;
                    *reinterpret_cast<float2*>(outB + (size_t)(r0 + 8) * ODIM + col) = v1;
                }
            }
        }
    }
}

// ---------------- kernel 3: local attention, conflict-free layouts ----------------
#define SPAD 72
#define ATTN_SMEM ((2 * 64 * SPAD + 2 * 64 * 64 + 512) * 4)

__global__ void __launch_bounds__(256)
attn_kernel(float* __restrict__ out)
{
    extern __shared__ float smf[];
    float* Qs  = smf;                         // [64][SPAD]
    float* Ss  = smf + 64 * SPAD;             // [64][SPAD]
    float* Kt  = smf + 2 * 64 * SPAD;         // [64][64]  Kt[d][k]
    float* Vs  = Kt + 64 * 64;                // [64][64]
    float* red = Vs + 64 * 64;                // [512]

    const int b = blockIdx.x >> 2;
    const int h = blockIdx.x & 3;
    const int tid = threadIdx.x;
    const float* Qg = g_QKV + ((size_t)(0 * 4 + h) * BATCH + b) * ODIM;
    const float* Kg = g_QKV + ((size_t)(1 * 4 + h) * BATCH + b) * ODIM;
    const float* Vg = g_QKV + ((size_t)(2 * 4 + h) * BATCH + b) * ODIM;

#pragma unroll
    for (int j = 0; j < 4; j++) {
        int f = tid + 256 * j;
        int r = f >> 4;
        int c = (f & 15) * 4;
        float4 qv = *reinterpret_cast<const float4*>(Qg + r * 64 + c);
        float4 vv = *reinterpret_cast<const float4*>(Vg + r * 64 + c);
        *reinterpret_cast<float4*>(Qs + r * SPAD + c) = qv;
        *reinterpret_cast<float4*>(Vs + r * 64 + c) = vv;
        int kr = f & 63;
        int c4 = (f >> 6) * 4;
        float4 kv = *reinterpret_cast<const float4*>(Kg + kr * 64 + c4);
        Kt[(c4 + 0) * 64 + kr] = kv.x;
        Kt[(c4 + 1) * 64 + kr] = kv.y;
        Kt[(c4 + 2) * 64 + kr] = kv.z;
        Kt[(c4 + 3) * 64 + kr] = kv.w;
    }
    __syncthreads();

    const int tx = tid & 15, ty = tid >> 4;
    const int q0 = ty * 4, k0 = tx * 4;

    float s[4][4];
#pragma unroll
    for (int i = 0; i < 4; i++)
#pragma unroll
        for (int j = 0; j < 4; j++) s[i][j] = 0.f;

    for (int d = 0; d < 64; d += 4) {
        float4 q4[4];
#pragma unroll
        for (int i = 0; i < 4; i++)
            q4[i] = *reinterpret_cast<const float4*>(Qs + (q0 + i) * SPAD + d);
#pragma unroll
        for (int dd = 0; dd < 4; dd++) {
            float4 kv = *reinterpret_cast<const float4*>(Kt + (d + dd) * 64 + k0);
#pragma unroll
            for (int i = 0; i < 4; i++) {
                float qv = (&q4[i].x)[dd];
                s[i][0] = fmaf(qv, kv.x, s[i][0]);
                s[i][1] = fmaf(qv, kv.y, s[i][1]);
                s[i][2] = fmaf(qv, kv.z, s[i][2]);
                s[i][3] = fmaf(qv, kv.w, s[i][3]);
            }
        }
    }
#pragma unroll
    for (int i = 0; i < 4; i++) {
        int qq = q0 + i;
        float4 o;
        o.x = s[i][0] - ((k0 + 0 > qq) ? 1e20f : 0.f);
        o.y = s[i][1] - ((k0 + 1 > qq) ? 1e20f : 0.f);
        o.z = s[i][2] - ((k0 + 2 > qq) ? 1e20f : 0.f);
        o.w = s[i][3] - ((k0 + 3 > qq) ? 1e20f : 0.f);
        *reinterpret_cast<float4*>(Ss + qq * SPAD + k0) = o;
    }
    __syncthreads();

    {
        const int kk = tid & 63;
        const int seg = tid >> 6;
        const int qb = seg * 16;
        float m = -3.4e38f;
#pragma unroll
        for (int i = 0; i < 16; i++) m = fmaxf(m, Ss[(qb + i) * SPAD + kk]);
        red[seg * 64 + kk] = m;
        __syncthreads();
        float M = fmaxf(fmaxf(red[kk], red[64 + kk]), fmaxf(red[128 + kk], red[192 + kk]));
        float ssum = 0.f;
#pragma unroll
        for (int i = 0; i < 16; i++) {
            float e = expf(Ss[(qb + i) * SPAD + kk] - M);
            Ss[(qb + i) * SPAD + kk] = e;
            ssum += e;
        }
        red[256 + seg * 64 + kk] = ssum;
        __syncthreads();
        float inv = 1.f / (red[256 + kk] + red[320 + kk] + red[384 + kk] + red[448 + kk]);
#pragma unroll
        for (int i = 0; i < 16; i++) Ss[(qb + i) * SPAD + kk] *= inv;
    }
    __syncthreads();

    const int d0 = tx * 4;
    float z[4][4];
#pragma unroll
    for (int i = 0; i < 4; i++)
#pragma unroll
        for (int j = 0; j < 4; j++) z[i][j] = 0.f;

    for (int k = 0; k < 64; k++) {
        float4 vv = *reinterpret_cast<const float4*>(Vs + k * 64 + d0);
        float av[4];
#pragma unroll
        for (int i = 0; i < 4; i++) av[i] = Ss[(q0 + i) * SPAD + k];
#pragma unroll
        for (int i = 0; i < 4; i++) {
            z[i][0] = fmaf(av[i], vv.x, z[i][0]);
            z[i][1] = fmaf(av[i], vv.y, z[i][1]);
            z[i][2] = fmaf(av[i], vv.z, z[i][2]);
            z[i][3] = fmaf(av[i], vv.w, z[i][3]);
        }
    }

    float* og = out + ((size_t)b * SEQLEN + h * LHEAD) * DQK;
#pragma unroll
    for (int i = 0; i < 4; i++) {
        float4 o4;
        o4.x = z[i][0] * 0.125f;
        o4.y = z[i][1] * 0.125f;
        o4.z = z[i][2] * 0.125f;
        o4.w = z[i][3] * 0.125f;
        *reinterpret_cast<float4*>(og + (q0 + i) * 64 + d0) = o4;
    }
}

// ---------------- launch ----------------
extern "C" void kernel_launch(void* const* d_in, const int* in_sizes, int n_in,
                              void* d_out, int out_size) {
    const float* seq = (const float*)d_in[0];
    const float* WQ  = (const float*)d_in[1];
    const float* bQ  = (const float*)d_in[2];
    const float* WK  = (const float*)d_in[3];
    const float* bK  = (const float*)d_in[4];
    const float* WV  = (const float*)d_in[5];
    const float* bV  = (const float*)d_in[6];
    float* out = (float*)d_out;

    cudaFuncSetAttribute(qkv_gemm_all, cudaFuncAttributeMaxDynamicSharedMemorySize, GEMM_SMEM);
    cudaFuncSetAttribute(attn_kernel, cudaFuncAttributeMaxDynamicSharedMemorySize, ATTN_SMEM);

    split_limbs_kernel<<<NTOT / 4 / 256, 256>>>(seq);
    qkv_gemm_all<<<dim3(32, 12), 384, GEMM_SMEM>>>(WQ, bQ, WK, bK, WV, bV);
    attn_kernel<<<BATCH * HEADS, 256, ATTN_SMEM>>>(out);
}

// round 16
// speedup vs baseline: 1.5066x; 1.0833x over previous
#include <cuda_runtime.h>
#include <cuda_bf16.h>
#include <cuda_fp16.h>
#include <cstdint>
#include <math.h>

// Problem constants
#define BATCH  128
#define HEADS  4
#define SEQLEN 256
#define EMB    64
#define DQK    64
#define LHEAD  64
#define KDIM   4096   // LHEAD * EMB
#define ODIM   4096   // LHEAD * DQK

// ---------------- scratch (device global; no allocation allowed) ----------------
__device__ __align__(16) float g_QKV[12 * BATCH * ODIM];   // [t*4+h][b][o]

// ---------------- PTX helpers ----------------
#define LDM_X4(R, ADDR) \
  asm volatile("ldmatrix.sync.aligned.m8n8.x4.shared.b16 {%0,%1,%2,%3}, [%4];" \
    : "=r"((R)[0]), "=r"((R)[1]), "=r"((R)[2]), "=r"((R)[3]) : "r"(ADDR))

#define MMA_BF16(C, A, Bv) \
  asm volatile("mma.sync.aligned.m16n8k16.row.col.f32.bf16.bf16.f32 " \
    "{%0,%1,%2,%3},{%4,%5,%6,%7},{%8,%9},{%0,%1,%2,%3};" \
    : "+f"((C)[0]), "+f"((C)[1]), "+f"((C)[2]), "+f"((C)[3]) \
    : "r"((A)[0]), "r"((A)[1]), "r"((A)[2]), "r"((A)[3]), "r"((Bv)[0]), "r"((Bv)[1]))

#define MMA_F16(C, A, Bv) \
  asm volatile("mma.sync.aligned.m16n8k16.row.col.f32.f16.f16.f32 " \
    "{%0,%1,%2,%3},{%4,%5,%6,%7},{%8,%9},{%0,%1,%2,%3};" \
    : "+f"((C)[0]), "+f"((C)[1]), "+f"((C)[2]), "+f"((C)[3]) \
    : "r"((A)[0]), "r"((A)[1]), "r"((A)[2]), "r"((A)[3]), "r"((Bv)[0]), "r"((Bv)[1]))

#define STSV2(ADDR, U0, U1) \
  asm volatile("st.shared.v2.b32 [%0], {%1,%2};" :: "r"(ADDR), "r"(U0), "r"(U1))

// Geometry: CTA tile 128(batch) x 128(outcols), BK=64, 256 threads.
// Warps 0-3: consumers 64x64 (warpM=(wid>>1)*64, warpN=(wid&1)*64).
// Warps 4-7: producers — LDG raw fp32 x and W, convert to limbs in-register, STS.
// Stage (row stride 72 elems = 144B, conflict-free ldmatrix):
//   AH[128][72] AL[128][72] WH[128][72] WL[128][72] -> 73728 B/stage, 2 stages.
#define BKC     64
#define NITER   (KDIM / BKC)   // 64
#define SROW    72
#define OFF_AH  0
#define OFF_AL  18432
#define OFF_WH  36864
#define OFF_WL  55296
#define STAGE   73728
#define GEMM_SMEM (2 * STAGE)  // 147456 B

// ---------------- kernel 1: merged QKV projection, split fused into producers ----
// grid (32, 12): y in [0,8) -> QK (t=y>>2, h=y&3), 3-term bf16;
//                y in [8,12) -> V (h=y-8), 2-term fp16.
__global__ void __launch_bounds__(256, 1)
qkv_gemm_all(const float* __restrict__ seq,
             const float* __restrict__ WQp, const float* __restrict__ bQp,
             const float* __restrict__ WKp, const float* __restrict__ bKp,
             const float* __restrict__ WVp, const float* __restrict__ bVp)
{
    extern __shared__ char smraw[];
    const uint32_t base = (uint32_t)__cvta_generic_to_shared(smraw);

    const int tid  = threadIdx.x;
    const int lane = tid & 31;
    const int wid  = tid >> 5;
    const int y    = blockIdx.y;
    const bool isV = (y >= 8);
    const int warpM = (wid >> 1) * 64;
    const int warpN = (wid & 1) * 64;
    const int p = tid - 128;               // producer thread index

    if (!isV) {
        const int t = y >> 2;
        const int h = y & 3;
        const float* Wp = (t == 0) ? WQp : WKp;
        const float* bp = ((t == 0) ? bQp : bKp) + h * ODIM + blockIdx.x * 128;
        const float* Wg = Wp + ((size_t)h * ODIM + (size_t)blockIdx.x * 128) * (size_t)KDIM;
        const float* Ax = seq + h * KDIM;   // row stride SEQLEN*EMB = 16384

        float acc[4][8][4];
#pragma unroll
        for (int a = 0; a < 4; a++)
#pragma unroll
            for (int b = 0; b < 8; b++)
#pragma unroll
                for (int c = 0; c < 4; c++) acc[a][b][c] = 0.f;

        float4 ar[16], wr[16];

#define QK_LDG(KT) do { \
    int k0 = (KT) * BKC; \
    _Pragma("unroll") \
    for (int j = 0; j < 16; j++) { \
        int f = p + 128 * j; int r = f >> 4; int c = (f & 15) * 4; \
        ar[j] = *reinterpret_cast<const float4*>(Ax + (size_t)r * (SEQLEN * EMB) + k0 + c); \
        wr[j] = *reinterpret_cast<const float4*>(Wg + (size_t)r * KDIM + k0 + c); \
    } \
} while (0)

#define QK_STS(S) do { \
    uint32_t sb = base + (uint32_t)(S) * STAGE; \
    _Pragma("unroll") \
    for (int j = 0; j < 16; j++) { \
        int f = p + 128 * j; int r = f >> 4; int c = (f & 15) * 4; \
        uint32_t off = (uint32_t)((r * SROW + c) * 2); \
        float4 v = ar[j]; \
        __nv_bfloat162 h0 = __floats2bfloat162_rn(v.x, v.y); \
        __nv_bfloat162 h1 = __floats2bfloat162_rn(v.z, v.w); \
        float2 f0 = __bfloat1622float2(h0); \
        float2 f1 = __bfloat1622float2(h1); \
        __nv_bfloat162 l0 = __floats2bfloat162_rn(v.x - f0.x, v.y - f0.y); \
        __nv_bfloat162 l1 = __floats2bfloat162_rn(v.z - f1.x, v.w - f1.y); \
        STSV2(sb + OFF_AH + off, reinterpret_cast<uint32_t&>(h0), reinterpret_cast<uint32_t&>(h1)); \
        STSV2(sb + OFF_AL + off, reinterpret_cast<uint32_t&>(l0), reinterpret_cast<uint32_t&>(l1)); \
        float4 w = wr[j]; \
        __nv_bfloat162 g0 = __floats2bfloat162_rn(w.x, w.y); \
        __nv_bfloat162 g1 = __floats2bfloat162_rn(w.z, w.w); \
        float2 e0 = __bfloat1622float2(g0); \
        float2 e1 = __bfloat1622float2(g1); \
        __nv_bfloat162 m0 = __floats2bfloat162_rn(w.x - e0.x, w.y - e0.y); \
        __nv_bfloat162 m1 = __floats2bfloat162_rn(w.z - e1.x, w.w - e1.y); \
        STSV2(sb + OFF_WH + off, reinterpret_cast<uint32_t&>(g0), reinterpret_cast<uint32_t&>(g1)); \
        STSV2(sb + OFF_WL + off, reinterpret_cast<uint32_t&>(m0), reinterpret_cast<uint32_t&>(m1)); \
    } \
} while (0)

#define QK_COMPUTE(S) do { \
    uint32_t sB = base + (uint32_t)(S) * STAGE; \
    _Pragma("unroll") \
    for (int ks = 0; ks < 4; ks++) { \
        uint32_t ah[4][4], al[4][4], bh[8][2], bl[8][2]; \
        int arl = lane & 15; \
        int ako = ks * 16 + ((lane >> 4) << 3); \
        _Pragma("unroll") \
        for (int mi = 0; mi < 4; mi++) { \
            uint32_t off = (uint32_t)(((warpM + mi * 16 + arl) * SROW + ako) * 2); \
            LDM_X4(ah[mi], sB + OFF_AH + off); \
            LDM_X4(al[mi], sB + OFF_AL + off); \
        } \
        int bnr = ((lane >> 4) << 3) + (lane & 7); \
        int bko = ks * 16 + (((lane >> 3) & 1) << 3); \
        _Pragma("unroll") \
        for (int jj = 0; jj < 4; jj++) { \
            uint32_t off = (uint32_t)(((warpN + jj * 16 + bnr) * SROW + bko) * 2); \
            uint32_t r4[4]; \
            LDM_X4(r4, sB + OFF_WH + off); \
            bh[2 * jj][0] = r4[0]; bh[2 * jj][1] = r4[1]; \
            bh[2 * jj + 1][0] = r4[2]; bh[2 * jj + 1][1] = r4[3]; \
            LDM_X4(r4, sB + OFF_WL + off); \
            bl[2 * jj][0] = r4[0]; bl[2 * jj][1] = r4[1]; \
            bl[2 * jj + 1][0] = r4[2]; bl[2 * jj + 1][1] = r4[3]; \
        } \
        _Pragma("unroll") \
        for (int mi = 0; mi < 4; mi++) \
        _Pragma("unroll") \
        for (int nj = 0; nj < 8; nj++) MMA_BF16(acc[mi][nj], ah[mi], bh[nj]); \
        _Pragma("unroll") \
        for (int mi = 0; mi < 4; mi++) \
        _Pragma("unroll") \
        for (int nj = 0; nj < 8; nj++) MMA_BF16(acc[mi][nj], ah[mi], bl[nj]); \
        _Pragma("unroll") \
        for (int mi = 0; mi < 4; mi++) \
        _Pragma("unroll") \
        for (int nj = 0; nj < 8; nj++) MMA_BF16(acc[mi][nj], al[mi], bh[nj]); \
    } \
} while (0)

        if (wid >= 4) { QK_LDG(0); QK_STS(0); }
        __syncthreads();

        for (int kt = 0; kt < NITER; kt++) {
            if (wid < 4) {
                QK_COMPUTE(kt & 1);
            } else if (kt + 1 < NITER) {
                QK_LDG(kt + 1);
                QK_STS((kt + 1) & 1);
            }
            __syncthreads();
        }

        if (wid < 4) {
            float* outB = g_QKV + (size_t)y * 128 * ODIM + blockIdx.x * 128;
            const int g = lane >> 2;
            const int q = lane & 3;
#pragma unroll
            for (int nj = 0; nj < 8; nj++) {
                int col = warpN + nj * 8 + 2 * q;
                float b0 = bp[col];
                float b1 = bp[col + 1];
#pragma unroll
                for (int mi = 0; mi < 4; mi++) {
                    int r0 = warpM + mi * 16 + g;
                    float2 v0; v0.x = acc[mi][nj][0] + b0; v0.y = acc[mi][nj][1] + b1;
                    float2 v1; v1.x = acc[mi][nj][2] + b0; v1.y = acc[mi][nj][3] + b1;
                    *reinterpret_cast<float2*>(outB + (size_t)r0 * ODIM + col) = v0;
                    *reinterpret_cast<float2*>(outB + (size_t)(r0 + 8) * ODIM + col) = v1;
                }
            }
        }
    } else {
        // ---------------- V path: 2-term fp16 (A exact hi/lo, W single fp16) ----
        const int h = y - 8;
        const float* bp = bVp + h * ODIM + blockIdx.x * 128;
        const float* Wg = WVp + ((size_t)h * ODIM + (size_t)blockIdx.x * 128) * (size_t)KDIM;
        const float* Ax = seq + h * KDIM;

        float acc[4][8][4];
#pragma unroll
        for (int a = 0; a < 4; a++)
#pragma unroll
            for (int b = 0; b < 8; b++)
#pragma unroll
                for (int c = 0; c < 4; c++) acc[a][b][c] = 0.f;

        float4 ar[16], wr[16];

#define V_LDG(KT) do { \
    int k0 = (KT) * BKC; \
    _Pragma("unroll") \
    for (int j = 0; j < 16; j++) { \
        int f = p + 128 * j; int r = f >> 4; int c = (f & 15) * 4; \
        ar[j] = *reinterpret_cast<const float4*>(Ax + (size_t)r * (SEQLEN * EMB) + k0 + c); \
        wr[j] = *reinterpret_cast<const float4*>(Wg + (size_t)r * KDIM + k0 + c); \
    } \
} while (0)

#define V_STS(S) do { \
    uint32_t sb = base + (uint32_t)(S) * STAGE; \
    _Pragma("unroll") \
    for (int j = 0; j < 16; j++) { \
        int f = p + 128 * j; int r = f >> 4; int c = (f & 15) * 4; \
        uint32_t off = (uint32_t)((r * SROW + c) * 2); \
        float4 v = ar[j]; \
        __half2 h0 = __floats2half2_rn(v.x, v.y); \
        __half2 h1 = __floats2half2_rn(v.z, v.w); \
        float2 f0 = __half22float2(h0); \
        float2 f1 = __half22float2(h1); \
        __half2 l0 = __floats2half2_rn(v.x - f0.x, v.y - f0.y); \
        __half2 l1 = __floats2half2_rn(v.z - f1.x, v.w - f1.y); \
        STSV2(sb + OFF_AH + off, reinterpret_cast<uint32_t&>(h0), reinterpret_cast<uint32_t&>(h1)); \
        STSV2(sb + OFF_AL + off, reinterpret_cast<uint32_t&>(l0), reinterpret_cast<uint32_t&>(l1)); \
        float4 w = wr[j]; \
        __half2 g0 = __floats2half2_rn(w.x, w.y); \
        __half2 g1 = __floats2half2_rn(w.z, w.w); \
        STSV2(sb + OFF_WH + off, reinterpret_cast<uint32_t&>(g0), reinterpret_cast<uint32_t&>(g1)); \
    } \
} while (0)

#define V_COMPUTE(S) do { \
    uint32_t sB = base + (uint32_t)(S) * STAGE; \
    _Pragma("unroll") \
    for (int ks = 0; ks < 4; ks++) { \
        uint32_t ah[4][4], al[4][4], bh[8][2]; \
        int arl = lane & 15; \
        int ako = ks * 16 + ((lane >> 4) << 3); \
        _Pragma("unroll") \
        for (int mi = 0; mi < 4; mi++) { \
            uint32_t off = (uint32_t)(((warpM + mi * 16 + arl) * SROW + ako) * 2); \
            LDM_X4(ah[mi], sB + OFF_AH + off); \
            LDM_X4(al[mi], sB + OFF_AL + off); \
        } \
        int bnr = ((lane >> 4) << 3) + (lane & 7); \
        int bko = ks * 16 + (((lane >> 3) & 1) << 3); \
        _Pragma("unroll") \
        for (int jj = 0; jj < 4; jj++) { \
            uint32_t off = (uint32_t)(((warpN + jj * 16 + bnr) * SROW + bko) * 2); \
            uint32_t r4[4]; \
            LDM_X4(r4, sB + OFF_WH + off); \
            bh[2 * jj][0] = r4[0]; bh[2 * jj][1] = r4[1]; \
            bh[2 * jj + 1][0] = r4[2]; bh[2 * jj + 1][1] = r4[3]; \
        } \
        _Pragma("unroll") \
        for (int mi = 0; mi < 4; mi++) \
        _Pragma("unroll") \
        for (int nj = 0; nj < 8; nj++) MMA_F16(acc[mi][nj], ah[mi], bh[nj]); \
        _Pragma("unroll") \
        for (int mi = 0; mi < 4; mi++) \
        _Pragma("unroll") \
        for (int nj = 0; nj < 8; nj++) MMA_F16(acc[mi][nj], al[mi], bh[nj]); \
    } \
} while (0)

        if (wid >= 4) { V_LDG(0); V_STS(0); }
        __syncthreads();

        for (int kt = 0; kt < NITER; kt++) {
            if (wid < 4) {
                V_COMPUTE(kt & 1);
            } else if (kt + 1 < NITER) {
                V_LDG(kt + 1);
                V_STS((kt + 1) & 1);
            }
            __syncthreads();
        }

        if (wid < 4) {
            float* outB = g_QKV + (size_t)(8 + h) * 128 * ODIM + blockIdx.x * 128;
            const int g = lane >> 2;
            const int q = lane & 3;
#pragma unroll
            for (int nj = 0; nj < 8; nj++) {
                int col = warpN + nj * 8 + 2 * q;
                float b0 = bp[col];
                float b1 = bp[col + 1];
#pragma unroll
                for (int mi = 0; mi < 4; mi++) {
                    int r0 = warpM + mi * 16 + g;
                    float2 v0; v0.x = acc[mi][nj][0] + b0; v0.y = acc[mi][nj][1] + b1;
                    float2 v1; v1.x = acc[mi][nj][2] + b0; v1.y = acc[mi][nj][3] + b1;
                    *reinterpret_cast<float2*>(outB + (size_t)r0 * ODIM + col) = v0;
                    *reinterpret_cast<float2*>(outB + (size_t)(r0 + 8) * ODIM + col) = v1;
                }
            }
        }
    }
}

// ---------------- kernel 2: local attention, conflict-free layouts ----------------
#define SPAD 72
#define ATTN_SMEM ((2 * 64 * SPAD + 2 * 64 * 64 + 512) * 4)

__global__ void __launch_bounds__(256)
attn_kernel(float* __restrict__ out)
{
    extern __shared__ float smf[];
    float* Qs  = smf;                         // [64][SPAD]
    float* Ss  = smf + 64 * SPAD;             // [64][SPAD]
    float* Kt  = smf + 2 * 64 * SPAD;         // [64][64]  Kt[d][k]
    float* Vs  = Kt + 64 * 64;                // [64][64]
    float* red = Vs + 64 * 64;                // [512]

    const int b = blockIdx.x >> 2;
    const int h = blockIdx.x & 3;
    const int tid = threadIdx.x;
    const float* Qg = g_QKV + ((size_t)(0 * 4 + h) * BATCH + b) * ODIM;
    const float* Kg = g_QKV + ((size_t)(1 * 4 + h) * BATCH + b) * ODIM;
    const float* Vg = g_QKV + ((size_t)(2 * 4 + h) * BATCH + b) * ODIM;

#pragma unroll
    for (int j = 0; j < 4; j++) {
        int f = tid + 256 * j;
        int r = f >> 4;
        int c = (f & 15) * 4;
        float4 qv = *reinterpret_cast<const float4*>(Qg + r * 64 + c);
        float4 vv = *reinterpret_cast<const float4*>(Vg + r * 64 + c);
        *reinterpret_cast<float4*>(Qs + r * SPAD + c) = qv;
        *reinterpret_cast<float4*>(Vs + r * 64 + c) = vv;
        int kr = f & 63;
        int c4 = (f >> 6) * 4;
        float4 kv = *reinterpret_cast<const float4*>(Kg + kr * 64 + c4);
        Kt[(c4 + 0) * 64 + kr] = kv.x;
        Kt[(c4 + 1) * 64 + kr] = kv.y;
        Kt[(c4 + 2) * 64 + kr] = kv.z;
        Kt[(c4 + 3) * 64 + kr] = kv.w;
    }
    __syncthreads();

    const int tx = tid & 15, ty = tid >> 4;
    const int q0 = ty * 4, k0 = tx * 4;

    float s[4][4];
#pragma unroll
    for (int i = 0; i < 4; i++)
#pragma unroll
        for (int j = 0; j < 4; j++) s[i][j] = 0.f;

    for (int d = 0; d < 64; d += 4) {
        float4 q4[4];
#pragma unroll
        for (int i = 0; i < 4; i++)
            q4[i] = *reinterpret_cast<const float4*>(Qs + (q0 + i) * SPAD + d);
#pragma unroll
        for (int dd = 0; dd < 4; dd++) {
            float4 kv = *reinterpret_cast<const float4*>(Kt + (d + dd) * 64 + k0);
#pragma unroll
            for (int i = 0; i < 4; i++) {
                float qv = (&q4[i].x)[dd];
                s[i][0] = fmaf(qv, kv.x, s[i][0]);
                s[i][1] = fmaf(qv, kv.y, s[i][1]);
                s[i][2] = fmaf(qv, kv.z, s[i][2]);
                s[i][3] = fmaf(qv, kv.w, s[i][3]);
            }
        }
    }
#pragma unroll
    for (int i = 0; i < 4; i++) {
        int qq = q0 + i;
        float4 o;
        o.x = s[i][0] - ((k0 + 0 > qq) ? 1e20f : 0.f);
        o.y = s[i][1] - ((k0 + 1 > qq) ? 1e20f : 0.f);
        o.z = s[i][2] - ((k0 + 2 > qq) ? 1e20f : 0.f);
        o.w = s[i][3] - ((k0 + 3 > qq) ? 1e20f : 0.f);
        *reinterpret_cast<float4*>(Ss + qq * SPAD + k0) = o;
    }
    __syncthreads();

    // softmax over QUERY axis (per key column), 256-thread parallel
    {
        const int kk = tid & 63;
        const int seg = tid >> 6;
        const int qb = seg * 16;
        float m = -3.4e38f;
#pragma unroll
        for (int i = 0; i < 16; i++) m = fmaxf(m, Ss[(qb + i) * SPAD + kk]);
        red[seg * 64 + kk] = m;
        __syncthreads();
        float M = fmaxf(fmaxf(red[kk], red[64 + kk]), fmaxf(red[128 + kk], red[192 + kk]));
        float ssum = 0.f;
#pragma unroll
        for (int i = 0; i < 16; i++) {
            float e = expf(Ss[(qb + i) * SPAD + kk] - M);
            Ss[(qb + i) * SPAD + kk] = e;
            ssum += e;
        }
        red[256 + seg * 64 + kk] = ssum;
        __syncthreads();
        float inv = 1.f / (red[256 + kk] + red[320 + kk] + red[384 + kk] + red[448 + kk]);
#pragma unroll
        for (int i = 0; i < 16; i++) Ss[(qb + i) * SPAD + kk] *= inv;
    }
    __syncthreads();

    const int d0 = tx * 4;
    float z[4][4];
#pragma unroll
    for (int i = 0; i < 4; i++)
#pragma unroll
        for (int j = 0; j < 4; j++) z[i][j] = 0.f;

    for (int k = 0; k < 64; k++) {
        float4 vv = *reinterpret_cast<const float4*>(Vs + k * 64 + d0);
        float av[4];
#pragma unroll
        for (int i = 0; i < 4; i++) av[i] = Ss[(q0 + i) * SPAD + k];
#pragma unroll
        for (int i = 0; i < 4; i++) {
            z[i][0] = fmaf(av[i], vv.x, z[i][0]);
            z[i][1] = fmaf(av[i], vv.y, z[i][1]);
            z[i][2] = fmaf(av[i], vv.z, z[i][2]);
            z[i][3] = fmaf(av[i], vv.w, z[i][3]);
        }
    }

    float* og = out + ((size_t)b * SEQLEN + h * LHEAD) * DQK;
#pragma unroll
    for (int i = 0; i < 4; i++) {
        float4 o4;
        o4.x = z[i][0] * 0.125f;
        o4.y = z[i][1] * 0.125f;
        o4.z = z[i][2] * 0.125f;
        o4.w = z[i][3] * 0.125f;
        *reinterpret_cast<float4*>(og + (q0 + i) * 64 + d0) = o4;
    }
}

// ---------------- launch ----------------
extern "C" void kernel_launch(void* const* d_in, const int* in_sizes, int n_in,
                              void* d_out, int out_size) {
    const float* seq = (const float*)d_in[0];
    const float* WQ  = (const float*)d_in[1];
    const float* bQ  = (const float*)d_in[2];
    const float* WK  = (const float*)d_in[3];
    const float* bK  = (const float*)d_in[4];
    const float* WV  = (const float*)d_in[5];
    const float* bV  = (const float*)d_in[6];
    float* out = (float*)d_out;

    cudaFuncSetAttribute(qkv_gemm_all, cudaFuncAttributeMaxDynamicSharedMemorySize, GEMM_SMEM);
    cudaFuncSetAttribute(attn_kernel, cudaFuncAttributeMaxDynamicSharedMemorySize, ATTN_SMEM);

    qkv_gemm_all<<<dim3(32, 12), 256, GEMM_SMEM>>>(seq, WQ, bQ, WK, bK, WV, bV);
    attn_kernel<<<BATCH * HEADS, 256, ATTN_SMEM>>>(out);
}